// round 2
// baseline (speedup 1.0000x reference)
#include <cuda_runtime.h>

#define BNN 16384   // 16*32*32

// ---------------- scratch (device globals; no allocation allowed) ----------
__device__ float g_Koa[512*128];
__device__ float g_Qoa[512*128];
__device__ float g_Voa[512*128];
__device__ float g_Vop[512*128];
__device__ float g_Ko [512*128];
__device__ float g_Qo [512*128];
__device__ float g_AVO[512*128];
__device__ float g_S  [512*128];
__device__ float g_wfo[512*128];
__device__ float g_A  [512*64];
__device__ float g_C  [512*64];
__device__ float g_woa[512*32];

__device__ __forceinline__ float dot4(float4 a, float4 b){
    return a.x*b.x + a.y*b.y + a.z*b.z + a.w*b.w;
}

// ---------------- kernel 1: the 7 linear projections ------------------------
// grid (16 b, 7 matrix, 4 d-slice), 256 threads.
// m=0 K_oa, 1 Q_oa, 2 V_oa, 3 V_op (obs|policy), 4 K_o, 5 Q_o, 6 AVO
__global__ __launch_bounds__(256) void proj_kernel(
    const float* __restrict__ states, const float* __restrict__ policies,
    const float* __restrict__ actions,
    const float* __restrict__ Wk_oa, const float* __restrict__ Wq_oa,
    const float* __restrict__ Wv_oa, const float* __restrict__ Wk_o,
    const float* __restrict__ Wq_o,  const float* __restrict__ Wv_o)
{
    __shared__ float IN [32*148];
    __shared__ float Wsm[32*148];
    int b = blockIdx.x, m = blockIdx.y, dz = blockIdx.z;
    int tid = threadIdx.x;
    int E = (m < 4) ? 144 : 128;
    const float* W = (m==0)?Wk_oa:(m==1)?Wq_oa:(m<=3)?Wv_oa:(m==4)?Wk_o:(m==5)?Wq_o:Wv_o;
    float* OUT = (m==0)?g_Koa:(m==1)?g_Qoa:(m==2)?g_Voa:(m==3)?g_Vop:(m==4)?g_Ko:(m==5)?g_Qo:g_AVO;

    for (int idx = tid; idx < 32*E; idx += 256) {
        int a = idx / E, e = idx - a*E;
        float v;
        if (e < 128) v = states[(b*32+a)*128 + e];
        else {
            int c = e - 128;
            v = (m == 3) ? policies[(b*32+a)*16 + c] : actions[(b*32+a)*16 + c];
        }
        IN[a*148 + e] = v;
    }
    for (int idx = tid; idx < 32*E; idx += 256) {
        int r = idx / E, e = idx - r*E;
        Wsm[r*148 + e] = W[(dz*32+r)*E + e];
    }
    __syncthreads();

    int r = tid & 31, g = tid >> 5;          // r = output dim in slice, g = agent group
    float acc0=0.f, acc1=0.f, acc2=0.f, acc3=0.f;
    const float4* wr = (const float4*)(Wsm + r*148);
    const float4* x0 = (const float4*)(IN + (g*4+0)*148);
    const float4* x1 = (const float4*)(IN + (g*4+1)*148);
    const float4* x2 = (const float4*)(IN + (g*4+2)*148);
    const float4* x3 = (const float4*)(IN + (g*4+3)*148);
    int nch = E >> 2;
    #pragma unroll 4
    for (int e4 = 0; e4 < nch; e4++) {
        float4 w = wr[e4];
        acc0 += dot4(w, x0[e4]);
        acc1 += dot4(w, x1[e4]);
        acc2 += dot4(w, x2[e4]);
        acc3 += dot4(w, x3[e4]);
    }
    int dg = dz*32 + r;
    OUT[(b*32 + g*4+0)*128 + dg] = acc0;
    OUT[(b*32 + g*4+1)*128 + dg] = acc1;
    OUT[(b*32 + g*4+2)*128 + dg] = acc2;
    OUT[(b*32 + g*4+3)*128 + dg] = acc3;
}

// ---------------- kernel 2: both attention branches -------------------------
// grid (16 b, 4 k-quarter), 256 threads. Warp per key-row k; lanes = i (softmax dim).
__global__ __launch_bounds__(256) void att_kernel(float* __restrict__ out)
{
    __shared__ float Qs[32*132];
    __shared__ float Vs[32*132];
    __shared__ float Ks[8*132];
    __shared__ float ws[8*33];
    int b = blockIdx.x, kq = blockIdx.y, tid = threadIdx.x;

    for (int p = 0; p < 2; p++) {
        const float* Qp = p ? g_Qo  : g_Qoa;
        const float* Kp = p ? g_Ko  : g_Koa;
        const float* Vp = p ? g_AVO : g_Voa;
        if (p) __syncthreads();
        for (int idx = tid; idx < 32*128; idx += 256) {
            int a = idx >> 7, e = idx & 127;
            Qs[a*132+e] = Qp[(b*32+a)*128+e];
            Vs[a*132+e] = Vp[(b*32+a)*128+e];
        }
        for (int idx = tid; idx < 8*128; idx += 256) {
            int kk = idx >> 7, e = idx & 127;
            Ks[kk*132+e] = Kp[(b*32+kq*8+kk)*128+e];
        }
        __syncthreads();

        int kk = tid >> 5, i = tid & 31, k = kq*8 + kk;
        const float4* qr = (const float4*)(Qs + i*132);
        const float4* kr = (const float4*)(Ks + kk*132);
        float acc = 0.f;
        #pragma unroll 8
        for (int e4 = 0; e4 < 32; e4++) acc += dot4(qr[e4], kr[e4]);
        float v = acc * 0.08838834764831845f;   // 1/sqrt(128)
        float mx = v;
        #pragma unroll
        for (int off = 16; off; off >>= 1) mx = fmaxf(mx, __shfl_xor_sync(0xffffffffu, mx, off));
        float ex = __expf(v - mx);
        float sm = ex;
        #pragma unroll
        for (int off = 16; off; off >>= 1) sm += __shfl_xor_sync(0xffffffffu, sm, off);
        float w = ex / sm;
        out[(p ? 2*BNN : BNN) + (b*32+k)*32 + i] = w;
        if (!p) g_woa[(b*32+k)*32 + i] = w;
        ws[kk*33 + i] = w;
        __syncthreads();

        // weighted value sum: S[b,k,:] (p=0) / wfo = .../32 (p=1)
        int c4 = tid & 31;
        float4 a4 = make_float4(0.f,0.f,0.f,0.f);
        #pragma unroll 8
        for (int i2 = 0; i2 < 32; i2++) {
            float wv = ws[kk*33 + i2];
            float4 vv = ((const float4*)(Vs + i2*132))[c4];
            a4.x += wv*vv.x; a4.y += wv*vv.y; a4.z += wv*vv.z; a4.w += wv*vv.w;
        }
        float scale = p ? 0.03125f : 1.0f;
        float* So = p ? g_wfo : g_S;
        ((float4*)(So + (b*32+k)*128))[c4] =
            make_float4(a4.x*scale, a4.y*scale, a4.z*scale, a4.w*scale);
    }
}

// ---------------- kernel 3: fold attention outputs through W1 ----------------
// A[g,h] = wfo[g]·W1a[h] + (S[g]/32 - 0.05)·W1b[h] ; C[g,h] = (Δ[g]/32)·W1b[h]
// grid 64 = (16 b × 4 agent-quarter), 256 threads.
__global__ __launch_bounds__(256) void ac_kernel(const float* __restrict__ W1)
{
    __shared__ float Ws[64*132];
    __shared__ float Xs[8*3*128];
    int bx = blockIdx.x; int b = bx >> 2, jq = bx & 3;
    int tid = threadIdx.x;
    const float INV32 = 0.03125f;

    for (int idx = tid; idx < 8*128; idx += 256) {
        int a = idx >> 7, e = idx & 127;
        int ga = b*32 + jq*8 + a;
        Xs[(a*3+0)*128+e] = g_wfo[ga*128+e];
        Xs[(a*3+1)*128+e] = g_S[ga*128+e]*INV32 - 0.05f;
        Xs[(a*3+2)*128+e] = (g_Vop[ga*128+e] - g_Voa[ga*128+e])*INV32;
    }
    for (int idx = tid; idx < 64*128; idx += 256) {
        int h = idx >> 7, e = idx & 127;
        Ws[h*132+e] = W1[h*256 + e];                 // W1a half
    }
    __syncthreads();

    int h = tid & 63, grp = tid >> 6;   // 2 agents per thread group
    const float4* wr = (const float4*)(Ws + h*132);
    const float4* p00 = (const float4*)(Xs + ((grp*2+0)*3+0)*128);
    const float4* p01 = (const float4*)(Xs + ((grp*2+1)*3+0)*128);
    float a1_0 = 0.f, a1_1 = 0.f;
    #pragma unroll 8
    for (int e4 = 0; e4 < 32; e4++) {
        float4 w = wr[e4];
        a1_0 += dot4(w, p00[e4]);
        a1_1 += dot4(w, p01[e4]);
    }
    __syncthreads();
    for (int idx = tid; idx < 64*128; idx += 256) {
        int hh = idx >> 7, e = idx & 127;
        Ws[hh*132+e] = W1[hh*256 + 128 + e];         // W1b half
    }
    __syncthreads();

    const float4* p10 = (const float4*)(Xs + ((grp*2+0)*3+1)*128);
    const float4* p11 = (const float4*)(Xs + ((grp*2+1)*3+1)*128);
    const float4* p20 = (const float4*)(Xs + ((grp*2+0)*3+2)*128);
    const float4* p21 = (const float4*)(Xs + ((grp*2+1)*3+2)*128);
    float a2_0 = 0.f, a2_1 = 0.f, c_0 = 0.f, c_1 = 0.f;
    #pragma unroll 8
    for (int e4 = 0; e4 < 32; e4++) {
        float4 w = wr[e4];
        a2_0 += dot4(w, p10[e4]);
        a2_1 += dot4(w, p11[e4]);
        c_0  += dot4(w, p20[e4]);
        c_1  += dot4(w, p21[e4]);
    }
    int ga0 = b*32 + jq*8 + grp*2;
    g_A[(ga0+0)*64 + h] = a1_0 + a2_0;
    g_A[(ga0+1)*64 + h] = a1_1 + a2_1;
    g_C[(ga0+0)*64 + h] = c_0;
    g_C[(ga0+1)*64 + h] = c_1;
}

// ---------------- kernel 4: stream noise + final value ----------------------
// grid 512 = (b,k). Streams 32 j-rows of noise (512KB/block), reduces over i,
// projects onto W1b, leaky-relu, dot W2 -> value.
__global__ __launch_bounds__(256) void nf_kernel(
    const float* __restrict__ noise, const float* __restrict__ W1,
    const float* __restrict__ W2, float* __restrict__ out)
{
    __shared__ float  W1b[64*132];
    __shared__ float4 part4[8*32];
    __shared__ float  Msm[8*128];
    __shared__ float  Cs[8*64];
    __shared__ float  As[64];
    __shared__ float  W2s[64];
    __shared__ float  woas[8];
    __shared__ float  wpart[8][2];

    int bk = blockIdx.x;
    int b = bk >> 5;
    int tid = threadIdx.x;

    for (int idx = tid; idx < 64*128; idx += 256) {
        int h = idx >> 7, e = idx & 127;
        W1b[h*132+e] = W1[h*256 + 128 + e];
    }
    if (tid < 64) { As[tid] = g_A[bk*64 + tid]; W2s[tid] = W2[tid]; }

    int d4 = tid & 31, ip = tid >> 5;
    const float4* np = (const float4*)noise;
    int base0 = bk * 32768;                 // float4 units: 32 j * 1024
    int h = tid & 63, g = tid >> 6;
    int lane = tid & 31, half = (tid >> 5) & 1;

    for (int grp = 0; grp < 4; grp++) {
        for (int idx = tid; idx < 512; idx += 256) {
            int jj = idx >> 6, hh = idx & 63;
            Cs[jj*64+hh] = g_C[(b*32 + grp*8 + jj)*64 + hh];
        }
        if (tid < 8) woas[tid] = g_woa[bk*32 + grp*8 + tid];

        int base = base0 + grp*8*1024;
        float4 c0 = np[base + (ip    )*32 + d4];
        float4 c1 = np[base + (ip+ 8)*32 + d4];
        float4 c2 = np[base + (ip+16)*32 + d4];
        float4 c3 = np[base + (ip+24)*32 + d4];
        __syncthreads();

        for (int jj = 0; jj < 8; jj++) {
            float4 n0 = make_float4(0.f,0.f,0.f,0.f), n1 = n0, n2 = n0, n3 = n0;
            if (jj < 7) {
                int nb = base + (jj+1)*1024;
                n0 = np[nb + (ip    )*32 + d4];
                n1 = np[nb + (ip+ 8)*32 + d4];
                n2 = np[nb + (ip+16)*32 + d4];
                n3 = np[nb + (ip+24)*32 + d4];
            }
            float4 s;
            s.x = (c0.x+c1.x) + (c2.x+c3.x);
            s.y = (c0.y+c1.y) + (c2.y+c3.y);
            s.z = (c0.z+c1.z) + (c2.z+c3.z);
            s.w = (c0.w+c1.w) + (c2.w+c3.w);
            part4[ip*32 + d4] = s;
            __syncthreads();
            if (tid < 128) {
                const float* pf = (const float*)part4;
                float mval = 0.f;
                #pragma unroll
                for (int q = 0; q < 8; q++) mval += pf[q*128 + tid];
                Msm[jj*128 + tid] = mval;
            }
            __syncthreads();
            c0 = n0; c1 = n1; c2 = n2; c3 = n3;
        }

        const float4* wr = (const float4*)(W1b + h*132);
        #pragma unroll
        for (int rep = 0; rep < 2; rep++) {
            int jj = g + 4*rep;
            const float4* mr = (const float4*)(Msm + jj*128);
            float acc = 0.f;
            #pragma unroll 8
            for (int e4 = 0; e4 < 32; e4++) acc += dot4(wr[e4], mr[e4]);
            float pre = As[h] + woas[jj]*Cs[jj*64 + h] + 0.003125f*acc;
            float hv  = pre > 0.f ? pre : 0.01f*pre;      // leaky relu
            float val = hv * W2s[h];
            #pragma unroll
            for (int off = 16; off; off >>= 1) val += __shfl_down_sync(0xffffffffu, val, off);
            if (lane == 0) wpart[jj][half] = val;
        }
        __syncthreads();
        if (tid < 8) out[bk*32 + grp*8 + tid] = wpart[tid][0] + wpart[tid][1];
    }
}

// ---------------- launch -----------------------------------------------------
extern "C" void kernel_launch(void* const* d_in, const int* in_sizes, int n_in,
                              void* d_out, int out_size)
{
    const float* states   = (const float*)d_in[0];
    const float* policies = (const float*)d_in[1];
    const float* actions  = (const float*)d_in[2];
    const float* noise    = (const float*)d_in[3];
    const float* Wk_oa    = (const float*)d_in[4];
    const float* Wq_oa    = (const float*)d_in[5];
    const float* Wv_oa    = (const float*)d_in[6];
    const float* Wk_o     = (const float*)d_in[7];
    const float* Wq_o     = (const float*)d_in[8];
    const float* Wv_o     = (const float*)d_in[9];
    const float* W1       = (const float*)d_in[10];
    const float* W2       = (const float*)d_in[11];
    float* out = (float*)d_out;

    proj_kernel<<<dim3(16,7,4), 256>>>(states, policies, actions,
                                       Wk_oa, Wq_oa, Wv_oa, Wk_o, Wq_o, Wv_o);
    att_kernel<<<dim3(16,4), 256>>>(out);
    ac_kernel<<<64, 256>>>(W1);
    nf_kernel<<<512, 256>>>(noise, W1, W2, out);
}

// round 3
// speedup vs baseline: 1.4211x; 1.4211x over previous
#include <cuda_runtime.h>

#define BNN 16384   // 16*32*32

// ---------------- scratch (device globals) ----------------------------------
__device__ float g_Koa[512*128];
__device__ float g_Qoa[512*128];
__device__ float g_Voa[512*128];
__device__ float g_Vop[512*128];
__device__ float g_Ko [512*128];
__device__ float g_Qo [512*128];
__device__ float g_AVO[512*128];
__device__ float g_A  [512*64];
__device__ float g_C  [512*64];
__device__ float g_woa[512*32];
__device__ float g_M  [16384*128];   // per-(b,k,j) noise i-sum, 8MB (L2-resident)

__device__ __forceinline__ float dot4(float4 a, float4 b){
    return a.x*b.x + a.y*b.y + a.z*b.z + a.w*b.w;
}

// ---------------- kernel 1: the 7 linear projections ------------------------
__global__ __launch_bounds__(256) void proj_kernel(
    const float* __restrict__ states, const float* __restrict__ policies,
    const float* __restrict__ actions,
    const float* __restrict__ Wk_oa, const float* __restrict__ Wq_oa,
    const float* __restrict__ Wv_oa, const float* __restrict__ Wk_o,
    const float* __restrict__ Wq_o,  const float* __restrict__ Wv_o)
{
    __shared__ float IN [32*148];
    __shared__ float Wsm[32*148];
    int b = blockIdx.x, m = blockIdx.y, dz = blockIdx.z;
    int tid = threadIdx.x;
    int E = (m < 4) ? 144 : 128;
    const float* W = (m==0)?Wk_oa:(m==1)?Wq_oa:(m<=3)?Wv_oa:(m==4)?Wk_o:(m==5)?Wq_o:Wv_o;
    float* OUT = (m==0)?g_Koa:(m==1)?g_Qoa:(m==2)?g_Voa:(m==3)?g_Vop:(m==4)?g_Ko:(m==5)?g_Qo:g_AVO;

    for (int idx = tid; idx < 32*E; idx += 256) {
        int a = idx / E, e = idx - a*E;
        float v;
        if (e < 128) v = states[(b*32+a)*128 + e];
        else {
            int c = e - 128;
            v = (m == 3) ? policies[(b*32+a)*16 + c] : actions[(b*32+a)*16 + c];
        }
        IN[a*148 + e] = v;
    }
    for (int idx = tid; idx < 32*E; idx += 256) {
        int r = idx / E, e = idx - r*E;
        Wsm[r*148 + e] = W[(dz*32+r)*E + e];
    }
    __syncthreads();

    int r = tid & 31, g = tid >> 5;
    float acc0=0.f, acc1=0.f, acc2=0.f, acc3=0.f;
    const float4* wr = (const float4*)(Wsm + r*148);
    const float4* x0 = (const float4*)(IN + (g*4+0)*148);
    const float4* x1 = (const float4*)(IN + (g*4+1)*148);
    const float4* x2 = (const float4*)(IN + (g*4+2)*148);
    const float4* x3 = (const float4*)(IN + (g*4+3)*148);
    int nch = E >> 2;
    #pragma unroll 4
    for (int e4 = 0; e4 < nch; e4++) {
        float4 w = wr[e4];
        acc0 += dot4(w, x0[e4]);
        acc1 += dot4(w, x1[e4]);
        acc2 += dot4(w, x2[e4]);
        acc3 += dot4(w, x3[e4]);
    }
    int dg = dz*32 + r;
    OUT[(b*32 + g*4+0)*128 + dg] = acc0;
    OUT[(b*32 + g*4+1)*128 + dg] = acc1;
    OUT[(b*32 + g*4+2)*128 + dg] = acc2;
    OUT[(b*32 + g*4+3)*128 + dg] = acc3;
}

// ---------------- kernel 2: pure noise streaming reduction -------------------
// warp per (b,k,j) tile: sum 32 i-rows of 128 floats. No smem, no syncs.
__global__ __launch_bounds__(256) void reduce_kernel(const float4* __restrict__ np)
{
    int t = blockIdx.x*256 + threadIdx.x;
    int tile = t >> 5, lane = t & 31;
    const float4* p = np + (tile << 10) + lane;
    float4 acc = make_float4(0.f,0.f,0.f,0.f);
    #pragma unroll
    for (int i = 0; i < 32; i++) {
        float4 v = __ldcs(p + (i << 5));
        acc.x += v.x; acc.y += v.y; acc.z += v.z; acc.w += v.w;
    }
    ((float4*)g_M)[(tile << 5) + lane] = acc;
}

// ---------------- kernel 3: fused attention (both branches) + A/C fold -------
// grid (16 b, 4 agent-octet), 256 threads.
__global__ __launch_bounds__(256) void attac_kernel(
    const float* __restrict__ W1, float* __restrict__ out)
{
    __shared__ float sbig[8320];   // att: sQ(32*132=4224)+sV(32*128=4096); ac: W^T (128*65)
    __shared__ float sK[8*128];    // att K rows; later wfo rows
    __shared__ float sS[8*128];    // raw S (obs-action weighted value sum)
    __shared__ float sD[8*128];    // (Vop-Voa)/32
    float* sQ  = sbig;
    float* sV  = sbig + 4224;
    float* sWT = sbig;

    int b = blockIdx.x, q = blockIdx.y, tid = threadIdx.x;
    int kk = tid >> 5, i = tid & 31, k = q*8 + kk;

    for (int p = 0; p < 2; p++) {
        const float* Qp = p ? g_Qo  : g_Qoa;
        const float* Kp = p ? g_Ko  : g_Koa;
        const float* Vp = p ? g_AVO : g_Voa;
        if (p) __syncthreads();
        const float4* Q4 = (const float4*)(Qp + b*32*128);
        const float4* V4 = (const float4*)(Vp + b*32*128);
        for (int idx = tid; idx < 1024; idx += 256) {
            int a = idx >> 5, e4 = idx & 31;
            *(float4*)(sQ + a*132 + e4*4) = Q4[idx];
            ((float4*)sV)[idx] = V4[idx];
        }
        const float4* K4 = (const float4*)(Kp + (b*32 + q*8)*128);
        if (tid < 256) ((float4*)sK)[tid] = K4[tid];
        __syncthreads();

        const float4* qr = (const float4*)(sQ + i*132);
        const float4* kr = (const float4*)(sK + kk*128);
        float acc = 0.f;
        #pragma unroll
        for (int e4 = 0; e4 < 32; e4++) acc += dot4(qr[e4], kr[e4]);
        float v = acc * 0.08838834764831845f;   // 1/sqrt(128)
        float mx = v;
        #pragma unroll
        for (int off = 16; off; off >>= 1) mx = fmaxf(mx, __shfl_xor_sync(0xffffffffu, mx, off));
        float ex = __expf(v - mx);
        float sm = ex;
        #pragma unroll
        for (int off = 16; off; off >>= 1) sm += __shfl_xor_sync(0xffffffffu, sm, off);
        float w = ex / sm;
        out[(p ? 2*BNN : BNN) + (b*32+k)*32 + i] = w;
        if (!p) g_woa[(b*32+k)*32 + i] = w;
        if (p) __syncthreads();   // all score reads of sK done before wfo overwrites it

        float4 a4 = make_float4(0.f,0.f,0.f,0.f);
        #pragma unroll
        for (int i2 = 0; i2 < 32; i2++) {
            float wv = __shfl_sync(0xffffffffu, w, i2);
            float4 vv = ((const float4*)sV)[i2*32 + i];
            a4.x += wv*vv.x; a4.y += wv*vv.y; a4.z += wv*vv.z; a4.w += wv*vv.w;
        }
        if (!p) {
            ((float4*)sS)[kk*32 + i] = a4;
        } else {
            float4 sc = make_float4(a4.x*0.03125f, a4.y*0.03125f, a4.z*0.03125f, a4.w*0.03125f);
            ((float4*)sK)[kk*32 + i] = sc;    // wfo
        }
    }
    __syncthreads();   // sV reads done -> safe to overlay sWT; wfo/sS complete

    {
        int base = (b*32 + q*8)*128;
        for (int idx = tid; idx < 1024; idx += 256)
            sD[idx] = (g_Vop[base+idx] - g_Voa[base+idx]) * 0.03125f;
        for (int idx = tid; idx < 8192; idx += 256) {   // W1a^T (coalesced load)
            int hh = idx >> 7, e = idx & 127;
            sWT[e*65 + hh] = W1[hh*256 + e];
        }
    }
    __syncthreads();

    int h = tid & 63, grp = tid >> 6;    // 2 agents per grp
    const float* wf0 = sK + (grp*2  )*128;
    const float* wf1 = sK + (grp*2+1)*128;
    float accA0 = 0.f, accA1 = 0.f;
    #pragma unroll 4
    for (int e = 0; e < 128; e++) {
        float w = sWT[e*65 + h];
        accA0 += w*wf0[e]; accA1 += w*wf1[e];
    }
    __syncthreads();
    for (int idx = tid; idx < 8192; idx += 256) {       // W1b^T
        int hh = idx >> 7, e = idx & 127;
        sWT[e*65 + hh] = W1[hh*256 + 128 + e];
    }
    __syncthreads();

    const float* s0 = sS + grp*2*128; const float* s1 = s0 + 128;
    const float* d0 = sD + grp*2*128; const float* d1 = d0 + 128;
    float aS0=0.f, aS1=0.f, aD0=0.f, aD1=0.f, aW=0.f;
    #pragma unroll 4
    for (int e = 0; e < 128; e++) {
        float w = sWT[e*65 + h];
        aW  += w;
        aS0 += w*s0[e]; aS1 += w*s1[e];
        aD0 += w*d0[e]; aD1 += w*d1[e];
    }
    int ga = b*32 + q*8 + grp*2;
    g_A[ ga   *64 + h] = accA0 + 0.03125f*aS0 - 0.05f*aW;
    g_A[(ga+1)*64 + h] = accA1 + 0.03125f*aS1 - 0.05f*aW;
    g_C[ ga   *64 + h] = aD0;
    g_C[(ga+1)*64 + h] = aD1;
}

// ---------------- kernel 4: H = M @ W1b^T + epilogue -> value ----------------
// 128 blocks x 256 threads; block computes 128 rows x 64 h with 8x4 reg tiles.
__global__ __launch_bounds__(256) void gemm_kernel(
    const float* __restrict__ W1, const float* __restrict__ W2,
    float* __restrict__ out)
{
    __shared__ float Ms[128*36];    // 128 rows x 32-k chunk, pad 36
    __shared__ float Ws[32*68];     // W1b^T chunk [k][h], pad 68
    int R0 = blockIdx.x * 128;
    int tid = threadIdx.x;
    int tx = tid & 15, ty = tid >> 4;   // tx -> h quad, ty -> 8-row group

    float4 acc[8];
    #pragma unroll
    for (int qq = 0; qq < 8; qq++) acc[qq] = make_float4(0.f,0.f,0.f,0.f);

    for (int kc = 0; kc < 4; kc++) {
        __syncthreads();
        for (int idx = tid; idx < 1024; idx += 256) {
            int r = idx >> 3, c4 = idx & 7;
            *(float4*)(Ms + r*36 + c4*4) = ((const float4*)g_M)[(R0+r)*32 + kc*8 + c4];
        }
        for (int idx = tid; idx < 2048; idx += 256) {
            int hh = idx >> 5, k2 = idx & 31;
            Ws[k2*68 + hh] = W1[hh*256 + 128 + kc*32 + k2];
        }
        __syncthreads();
        #pragma unroll
        for (int k2 = 0; k2 < 32; k2++) {
            float4 w = *(const float4*)(Ws + k2*68 + tx*4);
            #pragma unroll
            for (int qq = 0; qq < 8; qq++) {
                float m = Ms[(ty*8+qq)*36 + k2];
                acc[qq].x += m*w.x; acc[qq].y += m*w.y;
                acc[qq].z += m*w.z; acc[qq].w += m*w.w;
            }
        }
    }

    float4 w2 = *(const float4*)(W2 + tx*4);
    #pragma unroll
    for (int qq = 0; qq < 8; qq++) {
        int row = R0 + ty*8 + qq;
        int bk = row >> 5, j = row & 31, b = row >> 10;
        float4 a4 = *(const float4*)(g_A + bk*64 + tx*4);
        float4 c4 = *(const float4*)(g_C + ((b<<5)+j)*64 + tx*4);
        float wo = g_woa[row];
        float px = a4.x + wo*c4.x + 0.003125f*acc[qq].x;
        float py = a4.y + wo*c4.y + 0.003125f*acc[qq].y;
        float pz = a4.z + wo*c4.z + 0.003125f*acc[qq].z;
        float pw = a4.w + wo*c4.w + 0.003125f*acc[qq].w;
        px = px > 0.f ? px : 0.01f*px;
        py = py > 0.f ? py : 0.01f*py;
        pz = pz > 0.f ? pz : 0.01f*pz;
        pw = pw > 0.f ? pw : 0.01f*pw;
        float val = px*w2.x + py*w2.y + pz*w2.z + pw*w2.w;
        #pragma unroll
        for (int off = 8; off; off >>= 1) val += __shfl_down_sync(0xffffffffu, val, off);
        if (tx == 0) out[row] = val;
    }
}

// ---------------- launch: fork noise reduction onto a side stream ------------
extern "C" void kernel_launch(void* const* d_in, const int* in_sizes, int n_in,
                              void* d_out, int out_size)
{
    const float* states   = (const float*)d_in[0];
    const float* policies = (const float*)d_in[1];
    const float* actions  = (const float*)d_in[2];
    const float* noise    = (const float*)d_in[3];
    const float* Wk_oa    = (const float*)d_in[4];
    const float* Wq_oa    = (const float*)d_in[5];
    const float* Wv_oa    = (const float*)d_in[6];
    const float* Wk_o     = (const float*)d_in[7];
    const float* Wq_o     = (const float*)d_in[8];
    const float* Wv_o     = (const float*)d_in[9];
    const float* W1       = (const float*)d_in[10];
    const float* W2       = (const float*)d_in[11];
    float* out = (float*)d_out;

    static cudaStream_t s2 = nullptr;
    static cudaEvent_t evA = nullptr, evB = nullptr;
    if (!s2) {
        cudaStreamCreateWithFlags(&s2, cudaStreamNonBlocking);
        cudaEventCreateWithFlags(&evA, cudaEventDisableTiming);
        cudaEventCreateWithFlags(&evB, cudaEventDisableTiming);
    }

    // fork: noise reduction runs concurrently with proj+attac
    cudaEventRecord(evA, 0);
    cudaStreamWaitEvent(s2, evA, 0);
    reduce_kernel<<<2048, 256, 0, s2>>>((const float4*)noise);
    cudaEventRecord(evB, s2);

    proj_kernel<<<dim3(16,7,4), 256>>>(states, policies, actions,
                                       Wk_oa, Wq_oa, Wv_oa, Wk_o, Wq_o, Wv_o);
    attac_kernel<<<dim3(16,4), 256>>>(W1, out);

    cudaStreamWaitEvent(0, evB, 0);
    gemm_kernel<<<128, 256>>>(W1, W2, out);
}